// round 5
// baseline (speedup 1.0000x reference)
#include <cuda_runtime.h>

#define B_    4
#define T_    32
#define C_    132
#define N_    512
#define K_    16
#define HID_  256
#define OUTG  1024      // 4*HID
#define KB0   132       // K-dim of G0 matmul
#define KB1   260       // K-dim of G1 matmul
#define NBLK  296       // persistent grid: 2 blocks/SM x 148 SMs

#define LAYER_SZ (B_*T_*260*N_)           // 17039360
#define HF_OFF   LAYER_SZ
#define CF_OFF   (HF_OFF + B_*HID_*N_)    // +524288
#define GI_OFF   (CF_OFF + B_*HID_*N_)    // +524288

// -------- scratch (static device arrays; no runtime allocation) --------
__device__ float d_g0[(size_t)B_*T_*N_*OUTG];   // [bt][n][o]   268 MB
__device__ float d_g1[B_*N_*OUTG];              // [b][m][o]      8 MB
__device__ float d_hwp[B_*KB1*N_];              // [b][c][n]  c: 0..3 pos, 4..259 h
__device__ float d_c[2][B_*N_*HID_];            // double-buffered cell state
__device__ float d_wt0[KB0*OUTG];               // transposed adjusted W for G0
__device__ float d_wt1[KB1*OUTG];               // transposed W for G1
__device__ int   d_gidx[B_*T_*N_*K_];

// -------- persistent-kernel sync state --------
__device__ unsigned g_arrive = 0;
__device__ unsigned g_gen    = 0;   // monotone across launches (base read at start)
__device__ unsigned g_ticket = 0;   // reset by k_prep_w each launch

__device__ __forceinline__ void gsync(unsigned target) {
    __syncthreads();
    if (threadIdx.x == 0) {
        __threadfence();                       // release + L1 invalidate (CCTL.IVALL)
        unsigned a = atomicAdd(&g_arrive, 1);
        if (a == NBLK - 1) {
            g_arrive = 0;
            __threadfence();
            atomicExch(&g_gen, target);
        } else {
            while ((int)(*(volatile unsigned*)&g_gen - target) < 0) { }
            __threadfence();                   // acquire + L1 invalidate
        }
    }
    __syncthreads();
}

typedef unsigned long long u64;
__device__ __forceinline__ u64 ffma2(u64 a, u64 b, u64 c) {
    u64 d;
    asm("fma.rn.f32x2 %0,%1,%2,%3;" : "=l"(d) : "l"(a), "l"(b), "l"(c));
    return d;
}
__device__ __forceinline__ u64 dup2(float x) {
    u64 r;
    asm("mov.b64 %0,{%1,%1};" : "=l"(r) : "f"(x));
    return r;
}
__device__ __forceinline__ void unpack2(u64 v, float& x, float& y) {
    asm("mov.b64 {%0,%1},%2;" : "=f"(x), "=f"(y) : "l"(v));
}

__device__ __forceinline__ float sigf(float v) {
    return __fdividef(1.f, 1.f + __expf(-v));
}
__device__ __forceinline__ float tanh_(float v) {
    return 1.f - __fdividef(2.f, __expf(2.f * v) + 1.f);
}

// -------- weight repack (also resets the phase-0 ticket for this launch) ----
__global__ void k_prep_w(const float* __restrict__ w) {
    int tid = blockIdx.x * blockDim.x + threadIdx.x;
    if (tid == 0) g_ticket = 0;
    if (tid >= OUTG * KB1) return;
    int o = tid / KB1, c = tid % KB1;
    d_wt1[c * OUTG + o] = w[o * 392 + 132 + c];
    if (c < KB0) {
        float v = w[o * 392 + c];
        if (c < 4) v -= w[o * 392 + 132 + c];
        d_wt0[c * OUTG + o] = v;
    }
}

// -------- init: hwp[b][c][n] = pos(t=0) for c<4 else 0 ; c0 = 0 --------
__global__ void k_init(const float* __restrict__ x) {
    int tid = blockIdx.x * blockDim.x + threadIdx.x;
    const int total1 = B_ * KB1 * N_;
    if (tid < total1) {
        int n = tid % N_;
        int c = (tid / N_) % KB1;
        int b = tid / (KB1 * N_);
        float v = 0.f;
        if (c < 4) v = x[((size_t)(b * T_ + 0) * C_ + c) * N_ + n];
        d_hwp[tid] = v;
    } else {
        int id2 = tid - total1;
        if (id2 < B_ * N_ * HID_) d_c[0][id2] = 0.f;
    }
}

// -------- copy position channels into layer_output --------
__global__ void k_copy_pos(const float* __restrict__ x, float* __restrict__ out) {
    int tid = blockIdx.x * blockDim.x + threadIdx.x;
    if (tid >= B_ * T_ * 4 * N_) return;
    int n = tid % N_;
    int c = (tid / N_) & 3;
    int bt = tid / (4 * N_);
    out[((size_t)bt * 260 + c) * N_ + n] = x[((size_t)bt * C_ + c) * N_ + n];
}

// -------- KNN half-unit: 256 q-points of one (b,t); math identical to the
// passing round-4 kernel (XLA-CPU rounding + stable shift-insert) --------
__device__ void knn_item(const float* __restrict__ x, float* __restrict__ out,
                         int u, float* sm) {
    int bt = u >> 1, half = u & 1;
    int b = bt / T_, t = bt % T_;
    int tr = (t == 0) ? 0 : t - 1;
    float* rx = sm;
    float* ry = sm + 512;
    float* rz = sm + 1024;
    float* rr = sm + 1536;
    int tid = threadIdx.x;
    const float* rb = x + (size_t)(b * T_ + tr) * C_ * N_;
    for (int i = tid; i < N_; i += 256) {
        float a = rb[i], e = rb[N_ + i], f = rb[2 * N_ + i];
        rx[i] = a; ry[i] = e; rz[i] = f;
        rr[i] = __fadd_rn(__fadd_rn(__fmul_rn(a, a), __fmul_rn(e, e)),
                          __fmul_rn(f, f));
    }
    __syncthreads();
    int q = half * 256 + tid;
    const float* qb = x + (size_t)bt * C_ * N_;
    float qx = qb[q], qy = qb[N_ + q], qz = qb[2 * N_ + q];
    float qq = __fadd_rn(__fadd_rn(__fmul_rn(qx, qx), __fmul_rn(qy, qy)),
                         __fmul_rn(qz, qz));

    float bd[K_];
    int   bi[K_];
#pragma unroll
    for (int i = 0; i < K_; i++) { bd[i] = 3.4e38f; bi[i] = 0; }

    for (int m = 0; m < N_; m++) {
        float inner = __fmul_rn(qx, rx[m]);
        inner = fmaf(qy, ry[m], inner);
        inner = fmaf(qz, rz[m], inner);
        float d2 = __fsub_rn(__fadd_rn(qq, rr[m]), __fmul_rn(2.0f, inner));
        if (d2 < bd[K_ - 1]) {
            float cv = d2; int ci = m;
#pragma unroll
            for (int i = 0; i < K_; i++) {
                bool sm2 = d2 < bd[i];   // original d2 -> true shift chain (stable)
                float tf = bd[i]; int ti = bi[i];
                bd[i] = sm2 ? cv : bd[i];
                bi[i] = sm2 ? ci : bi[i];
                cv = sm2 ? tf : cv;
                ci = sm2 ? ti : ci;
            }
        }
    }
    int*   gi = d_gidx + ((size_t)bt * N_ + q) * K_;
    float* go = out + GI_OFF + ((size_t)bt * N_ + q) * K_;
#pragma unroll
    for (int i = 0; i < K_; i++) { gi[i] = bi[i]; go[i] = (float)bi[i]; }
    __syncthreads();   // smem reused by next item
}

// -------- FFMA2 tiled matmul tile: dst[n][o] = sum_c wt[c][o]*src[c][n] ----
// tile: 64 n x 128 o, 256 threads, micro-tile 4n x 8o (o-paired f32x2)
__device__ void mm_tile(const float* __restrict__ src, const float* __restrict__ wt,
                        float* __restrict__ dst, int K, int n0, int o0,
                        const float* __restrict__ bias,
                        float (&As)[2][8][128], float (&Xs)[2][8][64]) {
    const int NC = (K + 7) / 8;
    int tid = threadIdx.x;
    int tx = tid & 15;        // n: tx*4
    int ty = tid >> 4;        // o: ty*8

    u64 acc[4][4];
#pragma unroll
    for (int i = 0; i < 4; i++)
#pragma unroll
        for (int j = 0; j < 4; j++) acc[i][j] = 0ull;

    auto loadA = [&](int kc, int bf) {
#pragma unroll
        for (int r = 0; r < 4; r++) {
            int e = tid + r * 256;
            int cp = e >> 7, oo = e & 127;
            int c = kc * 8 + cp;
            As[bf][cp][oo] = (c < K) ? wt[c * OUTG + o0 + oo] : 0.f;
        }
    };
    auto loadX = [&](int kc, int bf) {
#pragma unroll
        for (int r = 0; r < 2; r++) {
            int e = tid + r * 256;
            int cp = e >> 6, nn = e & 63;
            int c = kc * 8 + cp;
            Xs[bf][cp][nn] = (c < K) ? src[(size_t)c * N_ + n0 + nn] : 0.f;
        }
    };

    loadA(0, 0); loadX(0, 0);
    __syncthreads();
    int buf = 0;
    for (int kc = 0; kc < NC; kc++) {
        if (kc + 1 < NC) { loadA(kc + 1, buf ^ 1); loadX(kc + 1, buf ^ 1); }
#pragma unroll
        for (int kk = 0; kk < 8; kk++) {
            ulonglong2 a01 = *(const ulonglong2*)&As[buf][kk][ty * 8];
            ulonglong2 a23 = *(const ulonglong2*)&As[buf][kk][ty * 8 + 4];
            float4 xv = *(const float4*)&Xs[buf][kk][tx * 4];
            u64 ap[4] = {a01.x, a01.y, a23.x, a23.y};
            u64 xd[4] = {dup2(xv.x), dup2(xv.y), dup2(xv.z), dup2(xv.w)};
#pragma unroll
            for (int i = 0; i < 4; i++)
#pragma unroll
                for (int j = 0; j < 4; j++)
                    acc[i][j] = ffma2(ap[i], xd[j], acc[i][j]);
        }
        __syncthreads();
        buf ^= 1;
    }

    float bv[8];
#pragma unroll
    for (int i = 0; i < 8; i++) bv[i] = 0.f;
    if (bias) {
#pragma unroll
        for (int i = 0; i < 8; i++) bv[i] = bias[o0 + ty * 8 + i];
    }
#pragma unroll
    for (int j = 0; j < 4; j++) {
        float f[8];
#pragma unroll
        for (int i = 0; i < 4; i++) unpack2(acc[i][j], f[2 * i], f[2 * i + 1]);
#pragma unroll
        for (int i = 0; i < 8; i++) f[i] += bv[i];
        float* dp = &dst[(size_t)(n0 + tx * 4 + j) * OUTG + o0 + ty * 8];
        *(float4*)dp       = make_float4(f[0], f[1], f[2], f[3]);
        *(float4*)(dp + 4) = make_float4(f[4], f[5], f[6], f[7]);
    }
}

// -------- per-(b,n) LSTM elementwise with gather + max over k --------
__device__ void lstm_unit(const float* __restrict__ x, float* __restrict__ out,
                          int b, int n, int t, int* sidx) {
    int bt = b * T_ + t;
    int o = threadIdx.x;

    __syncthreads();   // previous unit done with sidx
    if (o < K_) sidx[o] = d_gidx[((size_t)bt * N_ + n) * K_ + o];
    __syncthreads();

    const float* g0 = d_g0 + ((size_t)bt * N_ + n) * OUTG;
    float gi0 = g0[o], gf0 = g0[o + 256], go0 = g0[o + 512], gg0 = g0[o + 768];

    const float* cr  = d_c[t & 1] + (size_t)b * N_ * HID_;
    float*       cw  = d_c[(t & 1) ^ 1] + (size_t)b * N_ * HID_;
    const float* g1b = d_g1 + (size_t)b * N_ * OUTG;

    float hmax = -3.4e38f, cmax = -3.4e38f;
#pragma unroll 4
    for (int k = 0; k < K_; k++) {
        int m = sidx[k];
        const float* g1 = g1b + (size_t)m * OUTG;
        float gi = gi0 + g1[o];
        float gf = gf0 + g1[o + 256];
        float go = go0 + g1[o + 512];
        float gg = gg0 + g1[o + 768];
        float cp = cr[(size_t)m * HID_ + o];
        float i_ = sigf(gi), f_ = sigf(gf), oo_ = sigf(go), g_ = tanh_(gg);
        float cn = f_ * cp + i_ * g_;
        float hn = oo_ * tanh_(cn);
        hmax = fmaxf(hmax, hn);
        cmax = fmaxf(cmax, cn);
    }

    cw[(size_t)n * HID_ + o] = cmax;

    float* hwB = d_hwp + (size_t)b * KB1 * N_;
    hwB[(size_t)(4 + o) * N_ + n] = hmax;
    if (o < 4) hwB[(size_t)o * N_ + n] = x[((size_t)bt * C_ + o) * N_ + n];

    out[((size_t)bt * 260 + 4 + o) * N_ + n] = hmax;
    if (t == T_ - 1) {
        out[HF_OFF + ((size_t)b * HID_ + o) * N_ + n] = hmax;
        out[CF_OFF + ((size_t)b * HID_ + o) * N_ + n] = cmax;
    }
}

// -------- persistent scan kernel: phase0 (knn + all-g0) then 32 steps --------
__global__ __launch_bounds__(256, 2) void k_scan(const float* __restrict__ x,
                                                 const float* __restrict__ bias,
                                                 float* __restrict__ out) {
    __shared__ float As[2][8][128];
    __shared__ float Xs[2][8][64];
    __shared__ int sidx[K_];
    __shared__ unsigned s_word;

    if (threadIdx.x == 0) s_word = *(volatile unsigned*)&g_gen;
    __syncthreads();
    unsigned gen = s_word;

    // phase 0: dynamic queue — items 0..255 knn half-units, 256..8447 g0 tiles
    for (;;) {
        __syncthreads();
        if (threadIdx.x == 0) s_word = atomicAdd(&g_ticket, 1);
        __syncthreads();
        unsigned it = s_word;
        if (it >= 256u + 8192u) break;
        if (it < 256u) {
            knn_item(x, out, (int)it, &As[0][0][0]);
        } else {
            int tile = (int)it - 256;
            int bt = tile >> 6, rem = tile & 63;
            mm_tile(x + (size_t)bt * C_ * N_, d_wt0,
                    d_g0 + (size_t)bt * N_ * OUTG, KB0,
                    (rem & 7) * 64, (rem >> 3) * 128, bias, As, Xs);
        }
    }
    gsync(++gen);

    // sequential scan
    for (int t = 0; t < T_; t++) {
        if (blockIdx.x < 256) {
            int b = blockIdx.x >> 6, rem = blockIdx.x & 63;
            mm_tile(d_hwp + (size_t)b * KB1 * N_, d_wt1,
                    d_g1 + (size_t)b * N_ * OUTG, KB1,
                    (rem & 7) * 64, (rem >> 3) * 128, nullptr, As, Xs);
        }
        gsync(++gen);
        for (int u = blockIdx.x; u < B_ * N_; u += NBLK) {
            lstm_unit(x, out, u >> 9, u & 511, t, sidx);
        }
        gsync(++gen);
    }
}

extern "C" void kernel_launch(void* const* d_in, const int* in_sizes, int n_in,
                              void* d_out, int out_size) {
    const float* x    = (const float*)d_in[0];
    const float* w    = (const float*)d_in[1];
    const float* bias = (const float*)d_in[2];
    float* out = (float*)d_out;

    k_prep_w<<<(OUTG * KB1 + 255) / 256, 256>>>(w);
    {
        int initN = B_ * KB1 * N_ + B_ * N_ * HID_;
        k_init<<<(initN + 255) / 256, 256>>>(x);
    }
    k_copy_pos<<<(B_ * T_ * 4 * N_ + 255) / 256, 256>>>(x, out);
    k_scan<<<NBLK, 256>>>(x, bias, out);
}